// round 10
// baseline (speedup 1.0000x reference)
#include <cuda_runtime.h>
#include <cuda_fp16.h>
#include <cstdint>

// ---------------------------------------------------------------------------
// InflateHexToVertex, factored:
//   Z[j,t,b,v] = hex[b,t,:] @ W[j*D:(j+1)*D, :]   (mma.sync fp16 GEMM, f32 acc)
//   out[b,n,v] = bias[v] + sum_j (idx[n,j] >= 0) * Z[j, idx[n,j], b, v]
//
// Z fp16 (12.6 MB), L2-resident. Vertices are counting-sorted by t0 so each
// gather block (one 16-vertex chunk of a t0-bucket) stages Z[0,t0,:,:] in
// smem ONCE and reuses it: global Z reads drop 492 -> ~330 MB.
// ---------------------------------------------------------------------------

__device__ __half g_Zh[3 * 512 * 32 * 128];

// ---- bucketing scratch ------------------------------------------------------
#define NB 513                     // buckets: t0 in [0,512) plus bucket 512 for t0=-1
#define CHUNK 16
__device__ int g_cnt[NB];
__device__ int g_pos[NB];
__device__ int g_ord[20480];
__device__ int g_dT[2048], g_dS[2048], g_dL[2048];
__device__ int g_nchunks;

__device__ __forceinline__ uint32_t smem_u32(const void* p) {
    uint32_t a;
    asm("{ .reg .u64 t; cvta.to.shared.u64 t, %1; cvt.u32.u64 %0, t; }"
        : "=r"(a) : "l"(p));
    return a;
}

// int64 little-endian => every odd word is the sign extension of the even
// word; int32 data with values in [-1,T) fails this w.p. ~1. Warp 0 only.
__device__ __forceinline__ int detect_stride(const int* idxw) {
    int lo = idxw[2 * (threadIdx.x & 31)];
    int hi = idxw[2 * (threadIdx.x & 31) + 1];
    unsigned ok = __ballot_sync(0xffffffffu, hi == ((lo < 0) ? -1 : 0));
    return 1 + (ok == 0xffffffffu);
}

// ---- sort kernels ------------------------------------------------------------
__global__ void k_zero() {
    if (threadIdx.x < NB) g_cnt[threadIdx.x] = 0;
}

__global__ void k_hist(const int* __restrict__ idxw, int N) {
    __shared__ int sh_s;
    if (threadIdx.x < 32) {
        int s = detect_stride(idxw);
        if (threadIdx.x == 0) sh_s = s;
    }
    __syncthreads();
    int n = blockIdx.x * blockDim.x + threadIdx.x;
    if (n < N) {
        int t0 = idxw[(n * 3) * sh_s];
        atomicAdd(&g_cnt[t0 < 0 ? 512 : t0], 1);
    }
}

__global__ void k_scan(int N) {
    __shared__ int sh[1024];
    const int i = threadIdx.x;
    int cnt = (i < NB) ? g_cnt[i] : 0;
    sh[i] = cnt;
    __syncthreads();
    #pragma unroll
    for (int off = 1; off < 1024; off <<= 1) {
        int v = (i >= off) ? sh[i - off] : 0;
        __syncthreads();
        sh[i] += v;
        __syncthreads();
    }
    int excl = sh[i] - cnt;
    if (i < NB) g_pos[i] = excl;
    __syncthreads();

    int nch = (cnt + CHUNK - 1) / CHUNK;
    sh[i] = nch;
    __syncthreads();
    #pragma unroll
    for (int off = 1; off < 1024; off <<= 1) {
        int v = (i >= off) ? sh[i - off] : 0;
        __syncthreads();
        sh[i] += v;
        __syncthreads();
    }
    int chExcl = sh[i] - nch;
    if (i < NB) {
        for (int c = 0; c < nch; ++c) {
            g_dT[chExcl + c] = i;
            g_dS[chExcl + c] = excl + c * CHUNK;
            g_dL[chExcl + c] = min(CHUNK, cnt - c * CHUNK);
        }
    }
    if (i == 1023) g_nchunks = sh[1023];
}

__global__ void k_scatter(const int* __restrict__ idxw, int N) {
    __shared__ int sh_s;
    if (threadIdx.x < 32) {
        int s = detect_stride(idxw);
        if (threadIdx.x == 0) sh_s = s;
    }
    __syncthreads();
    int n = blockIdx.x * blockDim.x + threadIdx.x;
    if (n < N) {
        int t0 = idxw[(n * 3) * sh_s];
        int pos = atomicAdd(&g_pos[t0 < 0 ? 512 : t0], 1);
        g_ord[pos] = n;
    }
}

// ---- GEMM (R8 folded version, unchanged) -------------------------------------
#define OFF_A 0
#define OFF_B 32768
#define GEMM_SMEM 65536

__global__ void __launch_bounds__(256, 2)
gemm_z(const float* __restrict__ A, const float* __restrict__ W,
       int T, int B) {
    extern __shared__ char sm[];
    const uint32_t smb = smem_u32(sm);
    const int tid = threadIdx.x;
    const int wid = tid >> 5;
    const int lane = tid & 31;
    const int m0 = blockIdx.x * 128;

    #pragma unroll
    for (int it = 0; it < 8; ++it) {
        int p   = it * 256 + tid;
        int row = p >> 4;
        int c   = p & 15;
        const float* src = A + (size_t)(m0 + row) * 128 + c * 8;
        float4 f0 = *(const float4*)src;
        float4 f1 = *(const float4*)(src + 4);
        __half2 h[4] = {__floats2half2_rn(f0.x, f0.y), __floats2half2_rn(f0.z, f0.w),
                        __floats2half2_rn(f1.x, f1.y), __floats2half2_rn(f1.z, f1.w)};
        *(uint4*)(sm + OFF_A + row * 256 + ((c ^ (row & 7)) << 4)) = *(uint4*)h;
    }

    const int arow = wid * 16 + (lane & 15);
    const uint32_t a_base = smb + OFF_A + arow * 256;
    const int a_hi = lane >> 4;
    const int a_r7 = arow & 7;
    const uint32_t b_base = smb + OFF_B + (lane & 15) * 256;
    const int b_hi = lane >> 4;
    const int b_r7 = lane & 7;

    const int r  = lane >> 2;
    const int q2 = (lane & 3) * 2;
    const int mA = m0 + wid * 16 + r;
    const int mB = mA + 8;
    const int bA = mA / T, tA = mA - bA * T;
    const int bB = mB / T, tB = mB - bB * T;

    for (int j = 0; j < 3; ++j) {
        #pragma unroll
        for (int it = 0; it < 8; ++it) {
            int p  = it * 256 + tid;
            int k  = p >> 4;
            int cn = p & 15;
            const float* src = W + ((size_t)j * 128 + k) * 128 + cn * 8;
            float4 f0 = *(const float4*)src;
            float4 f1 = *(const float4*)(src + 4);
            __half2 h[4] = {__floats2half2_rn(f0.x, f0.y), __floats2half2_rn(f0.z, f0.w),
                            __floats2half2_rn(f1.x, f1.y), __floats2half2_rn(f1.z, f1.w)};
            *(uint4*)(sm + OFF_B + k * 256 + ((cn ^ (k & 7)) << 4)) = *(uint4*)h;
        }
        __syncthreads();

        float c[16][4];
        #pragma unroll
        for (int nb = 0; nb < 16; ++nb)
            #pragma unroll
            for (int q = 0; q < 4; ++q) c[nb][q] = 0.f;

        #pragma unroll
        for (int kb = 0; kb < 8; ++kb) {
            uint32_t a0, a1, a2, a3;
            uint32_t a_addr = a_base + (((2 * kb + a_hi) ^ a_r7) << 4);
            asm volatile("ldmatrix.sync.aligned.m8n8.x4.shared.b16 {%0,%1,%2,%3}, [%4];"
                         : "=r"(a0), "=r"(a1), "=r"(a2), "=r"(a3) : "r"(a_addr));
            #pragma unroll
            for (int nb2 = 0; nb2 < 8; ++nb2) {
                uint32_t b0, b1, b2, b3;
                uint32_t b_addr = b_base + kb * 4096
                                + (((2 * nb2 + b_hi) ^ b_r7) << 4);
                asm volatile("ldmatrix.sync.aligned.m8n8.x4.trans.shared.b16 "
                             "{%0,%1,%2,%3}, [%4];"
                             : "=r"(b0), "=r"(b1), "=r"(b2), "=r"(b3) : "r"(b_addr));
                asm volatile(
                    "mma.sync.aligned.m16n8k16.row.col.f32.f16.f16.f32 "
                    "{%0,%1,%2,%3}, {%4,%5,%6,%7}, {%8,%9}, {%0,%1,%2,%3};"
                    : "+f"(c[2*nb2][0]), "+f"(c[2*nb2][1]),
                      "+f"(c[2*nb2][2]), "+f"(c[2*nb2][3])
                    : "r"(a0), "r"(a1), "r"(a2), "r"(a3), "r"(b0), "r"(b1));
                asm volatile(
                    "mma.sync.aligned.m16n8k16.row.col.f32.f16.f16.f32 "
                    "{%0,%1,%2,%3}, {%4,%5,%6,%7}, {%8,%9}, {%0,%1,%2,%3};"
                    : "+f"(c[2*nb2+1][0]), "+f"(c[2*nb2+1][1]),
                      "+f"(c[2*nb2+1][2]), "+f"(c[2*nb2+1][3])
                    : "r"(a0), "r"(a1), "r"(a2), "r"(a3), "r"(b2), "r"(b3));
            }
        }

        __half* dstA = g_Zh + (((size_t)j * T + tA) * B + bA) * 128 + q2;
        __half* dstB = g_Zh + (((size_t)j * T + tB) * B + bB) * 128 + q2;
        #pragma unroll
        for (int nb = 0; nb < 16; ++nb) {
            *(__half2*)(dstA + nb * 8) = __floats2half2_rn(c[nb][0], c[nb][1]);
            *(__half2*)(dstB + nb * 8) = __floats2half2_rn(c[nb][2], c[nb][3]);
        }
        __syncthreads();
    }
}

// ---- bucketed gather ----------------------------------------------------------
// One chunk (<=16 vertices, all sharing t0) per block iteration. Z[0,t0,:,:]
// staged in smem once; per vertex only j=1,2 rows are read from L2.
__global__ void __launch_bounds__(256)
gather_bucket(const int* __restrict__ idxw,
              const float* __restrict__ bias,
              float* __restrict__ out, int N, int T, int B) {
    __shared__ uint4 shz[512];              // 8KB: Z[0,t0,b,v] for all (b,v8)
    __shared__ int sh_n[CHUNK], sh_t1[CHUNK], sh_t2[CHUNK];
    __shared__ int sh_s;

    const int tid = threadIdx.x;
    if (tid < 32) {
        int s = detect_stride(idxw);
        if (tid == 0) sh_s = s;
    }
    __syncthreads();
    const int s = sh_s;

    const uint4* Z16 = (const uint4*)g_Zh;
    const int rows = B * 16;                // uint4 per (j,t) row block

    // bias for this thread's v8 (constant across chunk loop: v8 = p & 15,
    // and p in {tid, tid+256} share the same low 4 bits)
    const int v8 = tid & 15;
    const float4 bsA = __ldg((const float4*)bias + v8 * 2);
    const float4 bsB = __ldg((const float4*)bias + v8 * 2 + 1);

    const int nch = g_nchunks;
    for (int c = blockIdx.x; c < nch; c += gridDim.x) {
        const int t0   = g_dT[c];
        const int strt = g_dS[c];
        const int len  = g_dL[c];

        if (t0 < T) {
            const uint4* zr = Z16 + (size_t)t0 * rows;
            for (int q = tid; q < rows; q += 256) shz[q] = zr[q];
        }
        if (tid < len) {
            int n = g_ord[strt + tid];
            sh_n[tid]  = n;
            sh_t1[tid] = idxw[(n * 3 + 1) * s];
            sh_t2[tid] = idxw[(n * 3 + 2) * s];
        }
        __syncthreads();

        const float m0 = (t0 < T) ? 1.0f : 0.0f;

        for (int p = tid; p < rows; p += 256) {
            const int b = p >> 4;
            // base = bias + m0 * Z0  (8 floats, reused for every vertex)
            float bse[8] = {bsA.x, bsA.y, bsA.z, bsA.w, bsB.x, bsB.y, bsB.z, bsB.w};
            if (t0 < T) {
                uint4 z0 = shz[p];
                float2 f0 = __half22float2(*(__half2*)&z0.x);
                float2 f1 = __half22float2(*(__half2*)&z0.y);
                float2 f2 = __half22float2(*(__half2*)&z0.z);
                float2 f3 = __half22float2(*(__half2*)&z0.w);
                bse[0] = fmaf(m0, f0.x, bse[0]); bse[1] = fmaf(m0, f0.y, bse[1]);
                bse[2] = fmaf(m0, f1.x, bse[2]); bse[3] = fmaf(m0, f1.y, bse[3]);
                bse[4] = fmaf(m0, f2.x, bse[4]); bse[5] = fmaf(m0, f2.y, bse[5]);
                bse[6] = fmaf(m0, f3.x, bse[6]); bse[7] = fmaf(m0, f3.y, bse[7]);
            }

            for (int i0 = 0; i0 < len; i0 += 2) {
                const bool h2 = (i0 + 1) < len;
                const int n0 = sh_n[i0];
                const int n1 = h2 ? sh_n[i0 + 1] : n0;
                int tv[4];
                tv[0] = sh_t1[i0];
                tv[1] = sh_t2[i0];
                tv[2] = h2 ? sh_t1[i0 + 1] : 0;
                tv[3] = h2 ? sh_t2[i0 + 1] : 0;

                // 4 loads in flight (j=1,2 for both vertices), clamped + masked
                uint4 z[4];
                float mk[4];
                #pragma unroll
                for (int i = 0; i < 4; ++i) {
                    int jj = 1 + (i & 1);
                    mk[i] = (tv[i] >= 0) ? 1.0f : 0.0f;
                    int tc = (tv[i] >= 0) ? tv[i] : 0;
                    z[i] = __ldcg(Z16 + (size_t)(jj * T + tc) * rows + p);
                }

                #pragma unroll
                for (int nn = 0; nn < 2; ++nn) {
                    if (nn == 1 && !h2) break;
                    float acc[8];
                    #pragma unroll
                    for (int e = 0; e < 8; ++e) acc[e] = bse[e];
                    #pragma unroll
                    for (int jj = 0; jj < 2; ++jj) {
                        const uint4 zv = z[nn * 2 + jj];
                        const float m = mk[nn * 2 + jj];
                        float2 f0 = __half22float2(*(__half2*)&zv.x);
                        float2 f1 = __half22float2(*(__half2*)&zv.y);
                        float2 f2 = __half22float2(*(__half2*)&zv.z);
                        float2 f3 = __half22float2(*(__half2*)&zv.w);
                        acc[0] = fmaf(m, f0.x, acc[0]); acc[1] = fmaf(m, f0.y, acc[1]);
                        acc[2] = fmaf(m, f1.x, acc[2]); acc[3] = fmaf(m, f1.y, acc[3]);
                        acc[4] = fmaf(m, f2.x, acc[4]); acc[5] = fmaf(m, f2.y, acc[5]);
                        acc[6] = fmaf(m, f3.x, acc[6]); acc[7] = fmaf(m, f3.y, acc[7]);
                    }
                    const int n = nn ? n1 : n0;
                    float* o = out + ((size_t)b * N + n) * 128 + v8 * 8;
                    __stcs((float4*)o, make_float4(acc[0], acc[1], acc[2], acc[3]));
                    __stcs((float4*)(o + 4), make_float4(acc[4], acc[5], acc[6], acc[7]));
                }
            }
        }
        __syncthreads();   // protect shz/sh_* before restaging
    }
}

extern "C" void kernel_launch(void* const* d_in, const int* in_sizes, int n_in,
                              void* d_out, int out_size) {
    const float* hex  = (const float*)d_in[0];   // (B, T, D) f32
    const int*   idxw = (const int*)d_in[1];     // (N, 3) int32 or int64
    const float* W    = (const float*)d_in[2];   // (3D, V) f32
    const float* bias = (const float*)d_in[3];   // (V,) f32
    float*       out  = (float*)d_out;           // (B, N, V) f32

    const int V      = in_sizes[3];              // 128
    const int threeD = in_sizes[2] / V;          // 384
    const int D      = threeD / 3;               // 128
    const int BT     = in_sizes[0] / D;          // B*T = 16384
    const int N      = in_sizes[1] / 3;          // 20000
    const int B      = out_size / (N * V);       // 32
    const int T      = BT / B;                   // 512

    cudaFuncSetAttribute(gemm_z, cudaFuncAttributeMaxDynamicSharedMemorySize,
                         GEMM_SMEM);

    k_zero<<<1, 1024>>>();
    k_hist<<<(N + 255) / 256, 256>>>(idxw, N);
    gemm_z<<<BT / 128, 256, GEMM_SMEM>>>(hex, W, T, B);
    k_scan<<<1, 1024>>>(N);
    k_scatter<<<(N + 255) / 256, 256>>>(idxw, N);
    gather_bucket<<<1536, 256>>>(idxw, bias, out, N, T, B);
}

// round 11
// speedup vs baseline: 1.3116x; 1.3116x over previous
#include <cuda_runtime.h>
#include <cuda_fp16.h>
#include <cstdint>

// ---------------------------------------------------------------------------
// InflateHexToVertex, factored:
//   Z[j,t,b,v] = hex[b,t,:] @ W[j*D:(j+1)*D, :]   (mma.sync fp16 GEMM, f32 acc)
//   out[b,n,v] = bias[v] + sum_j (idx[n,j] >= 0) * Z[j, idx[n,j], b, v]
//
// Z fp16 (12.6 MB), L2-resident. GEMM: one block per 128-row A tile; A and
// ALL THREE W_j tiles staged once (128 KB smem, single sync), then 3 compute
// passes. Gather: R6 shape (256 thr, 2 vertices, 6 loads in flight) -- the
// measured optimum across rounds 3/6/8/9/10.
// ---------------------------------------------------------------------------

__device__ __half g_Zh[3 * 512 * 32 * 128];

#define OFF_A 0
#define OFF_B 32768                     // B_j at OFF_B + j*32768
#define GEMM_SMEM 131072

__device__ __forceinline__ uint32_t smem_u32(const void* p) {
    uint32_t a;
    asm("{ .reg .u64 t; cvta.to.shared.u64 t, %1; cvt.u32.u64 %0, t; }"
        : "=r"(a) : "l"(p));
    return a;
}

// --- Z = hex(16384x128) @ W(384x128) via mma.sync ----------------------------
// Grid BT/128, 256 threads (8 warps). Stage A + W_0..2 once; for j=0..2
// compute 128x128 and write Z_j. Warp w owns rows w*16..w*16+15.
__global__ void __launch_bounds__(256, 1)
gemm_z(const float* __restrict__ A, const float* __restrict__ W,
       int T, int B) {
    extern __shared__ char sm[];
    const uint32_t smb = smem_u32(sm);
    const int tid = threadIdx.x;
    const int wid = tid >> 5;
    const int lane = tid & 31;
    const int m0 = blockIdx.x * 128;

    // ---- stage A tile: fp32 -> fp16, swizzled --------------------------------
    #pragma unroll
    for (int it = 0; it < 8; ++it) {
        int p   = it * 256 + tid;          // 2048 chunks
        int row = p >> 4;
        int c   = p & 15;
        const float* src = A + (size_t)(m0 + row) * 128 + c * 8;
        float4 f0 = *(const float4*)src;
        float4 f1 = *(const float4*)(src + 4);
        __half2 h[4] = {__floats2half2_rn(f0.x, f0.y), __floats2half2_rn(f0.z, f0.w),
                        __floats2half2_rn(f1.x, f1.y), __floats2half2_rn(f1.z, f1.w)};
        *(uint4*)(sm + OFF_A + row * 256 + ((c ^ (row & 7)) << 4)) = *(uint4*)h;
    }
    // ---- stage all three W_j tiles: W[j*128 + k][v], fp32 -> fp16, swizzled --
    #pragma unroll
    for (int it = 0; it < 24; ++it) {
        int p  = it * 256 + tid;           // 6144 chunks over 3 j-blocks
        int jj = p >> 11;                  // 0..2
        int q  = p & 2047;
        int k  = q >> 4;
        int cn = q & 15;
        const float* src = W + ((size_t)jj * 128 + k) * 128 + cn * 8;
        float4 f0 = *(const float4*)src;
        float4 f1 = *(const float4*)(src + 4);
        __half2 h[4] = {__floats2half2_rn(f0.x, f0.y), __floats2half2_rn(f0.z, f0.w),
                        __floats2half2_rn(f1.x, f1.y), __floats2half2_rn(f1.z, f1.w)};
        *(uint4*)(sm + OFF_B + jj * 32768 + k * 256 + ((cn ^ (k & 7)) << 4)) =
            *(uint4*)h;
    }
    __syncthreads();

    // ldmatrix lane addressing
    const int arow = wid * 16 + (lane & 15);
    const uint32_t a_base = smb + OFF_A + arow * 256;
    const int a_hi = lane >> 4;
    const int a_r7 = arow & 7;
    const uint32_t b_base0 = smb + OFF_B + (lane & 15) * 256;
    const int b_hi = lane >> 4;            // x4.trans: upper half-warp -> chunk+1
    const int b_r7 = lane & 7;

    // epilogue coords
    const int r  = lane >> 2;
    const int q2 = (lane & 3) * 2;
    const int mA = m0 + wid * 16 + r;
    const int mB = mA + 8;
    const int bA = mA / T, tA = mA - bA * T;
    const int bB = mB / T, tB = mB - bB * T;

    #pragma unroll
    for (int j = 0; j < 3; ++j) {
        const uint32_t b_base = b_base0 + j * 32768;

        float c[16][4];
        #pragma unroll
        for (int nb = 0; nb < 16; ++nb)
            #pragma unroll
            for (int q = 0; q < 4; ++q) c[nb][q] = 0.f;

        #pragma unroll
        for (int kb = 0; kb < 8; ++kb) {
            uint32_t a0, a1, a2, a3;
            uint32_t a_addr = a_base + (((2 * kb + a_hi) ^ a_r7) << 4);
            asm volatile("ldmatrix.sync.aligned.m8n8.x4.shared.b16 {%0,%1,%2,%3}, [%4];"
                         : "=r"(a0), "=r"(a1), "=r"(a2), "=r"(a3) : "r"(a_addr));
            #pragma unroll
            for (int nb2 = 0; nb2 < 8; ++nb2) {
                uint32_t b0, b1, b2, b3;
                uint32_t b_addr = b_base + kb * 4096
                                + (((2 * nb2 + b_hi) ^ b_r7) << 4);
                asm volatile("ldmatrix.sync.aligned.m8n8.x4.trans.shared.b16 "
                             "{%0,%1,%2,%3}, [%4];"
                             : "=r"(b0), "=r"(b1), "=r"(b2), "=r"(b3) : "r"(b_addr));
                asm volatile(
                    "mma.sync.aligned.m16n8k16.row.col.f32.f16.f16.f32 "
                    "{%0,%1,%2,%3}, {%4,%5,%6,%7}, {%8,%9}, {%0,%1,%2,%3};"
                    : "+f"(c[2*nb2][0]), "+f"(c[2*nb2][1]),
                      "+f"(c[2*nb2][2]), "+f"(c[2*nb2][3])
                    : "r"(a0), "r"(a1), "r"(a2), "r"(a3), "r"(b0), "r"(b1));
                asm volatile(
                    "mma.sync.aligned.m16n8k16.row.col.f32.f16.f16.f32 "
                    "{%0,%1,%2,%3}, {%4,%5,%6,%7}, {%8,%9}, {%0,%1,%2,%3};"
                    : "+f"(c[2*nb2+1][0]), "+f"(c[2*nb2+1][1]),
                      "+f"(c[2*nb2+1][2]), "+f"(c[2*nb2+1][3])
                    : "r"(a0), "r"(a1), "r"(a2), "r"(a3), "r"(b2), "r"(b3));
            }
        }

        // ---- epilogue: cvt fp16, write Z[j][t][b][v] ---------------------------
        __half* dstA = g_Zh + (((size_t)j * T + tA) * B + bA) * 128 + q2;
        __half* dstB = g_Zh + (((size_t)j * T + tB) * B + bB) * 128 + q2;
        #pragma unroll
        for (int nb = 0; nb < 16; ++nb) {
            *(__half2*)(dstA + nb * 8) = __floats2half2_rn(c[nb][0], c[nb][1]);
            *(__half2*)(dstB + nb * 8) = __floats2half2_rn(c[nb][2], c[nb][3]);
        }
    }
}

// --- out[b,n,:] = bias + sum_j Z[j, idx[n,j], b, :] --------------------------
// 2 vertices per block, 256 threads, 2 (b,v8) items per thread per vertex.
// All 6 Z loads per item issued back-to-back (MLP). Measured 83.4 us (R6).
__global__ void gather_out(const int* __restrict__ idxw,
                           const float* __restrict__ bias,
                           float* __restrict__ out, int N, int T, int B) {
    __shared__ int sh_t[6];
    const int n0 = blockIdx.x * 2;

    if (threadIdx.x < 32) {
        // int64 little-endian => every odd word is the sign extension of the
        // preceding word; int32 data with values in [-1,T) fails w.p. ~1.
        int lo = idxw[2 * threadIdx.x];
        int hi = idxw[2 * threadIdx.x + 1];
        unsigned ok = __ballot_sync(0xffffffffu, hi == ((lo < 0) ? -1 : 0));
        int s = 1 + (ok == 0xffffffffu);
        if (threadIdx.x < 6) sh_t[threadIdx.x] = idxw[(n0 * 3 + threadIdx.x) * s];
    }
    __syncthreads();

    int tt[6];
    #pragma unroll
    for (int i = 0; i < 6; ++i) tt[i] = sh_t[i];

    const uint4*  Z16 = (const uint4*)g_Zh;
    const float4* b4  = (const float4*)bias;
    const uint4   zz  = make_uint4(0u, 0u, 0u, 0u);

    const int total = B * 16;                 // 512 items per vertex pair
    for (int p = threadIdx.x; p < total; p += blockDim.x) {
        const int b  = p >> 4;
        const int v8 = p & 15;
        const size_t rowoff = (size_t)b * 16 + v8;

        uint4 z[6];
        #pragma unroll
        for (int i = 0; i < 6; ++i) {
            int j = i % 3;
            int t = tt[i];
            z[i] = (t >= 0)
                 ? __ldcg(Z16 + ((size_t)j * T + t) * (B * 16) + rowoff)
                 : zz;
        }

        float4 bsA = __ldg(b4 + v8 * 2);
        float4 bsB = __ldg(b4 + v8 * 2 + 1);

        #pragma unroll
        for (int nn = 0; nn < 2; ++nn) {
            float4 accA = bsA, accB = bsB;
            #pragma unroll
            for (int j = 0; j < 3; ++j) {
                uint4 zv = z[nn * 3 + j];
                float2 f0 = __half22float2(*(__half2*)&zv.x);
                float2 f1 = __half22float2(*(__half2*)&zv.y);
                float2 f2 = __half22float2(*(__half2*)&zv.z);
                float2 f3 = __half22float2(*(__half2*)&zv.w);
                accA.x += f0.x; accA.y += f0.y; accA.z += f1.x; accA.w += f1.y;
                accB.x += f2.x; accB.y += f2.y; accB.z += f3.x; accB.w += f3.y;
            }
            float* o = out + ((size_t)b * N + (n0 + nn)) * 128 + v8 * 8;
            __stcs((float4*)o, accA);
            __stcs((float4*)(o + 4), accB);
        }
    }
}

extern "C" void kernel_launch(void* const* d_in, const int* in_sizes, int n_in,
                              void* d_out, int out_size) {
    const float* hex  = (const float*)d_in[0];   // (B, T, D) f32
    const int*   idxw = (const int*)d_in[1];     // (N, 3) int32 or int64
    const float* W    = (const float*)d_in[2];   // (3D, V) f32
    const float* bias = (const float*)d_in[3];   // (V,) f32
    float*       out  = (float*)d_out;           // (B, N, V) f32

    const int V      = in_sizes[3];              // 128
    const int threeD = in_sizes[2] / V;          // 384
    const int D      = threeD / 3;               // 128
    const int BT     = in_sizes[0] / D;          // B*T = 16384
    const int N      = in_sizes[1] / 3;          // 20000
    const int B      = out_size / (N * V);       // 32
    const int T      = BT / B;                   // 512

    cudaFuncSetAttribute(gemm_z, cudaFuncAttributeMaxDynamicSharedMemorySize,
                         GEMM_SMEM);

    gemm_z<<<BT / 128, 256, GEMM_SMEM>>>(hex, W, T, B);

    gather_out<<<N / 2, 256>>>(idxw, bias, out, N, T, B);
}